// round 15
// baseline (speedup 1.0000x reference)
#include <cuda_runtime.h>
#include <cuda_bf16.h>
#include <cuda_fp16.h>
#include <cstdint>

#define Bc 2
#define Sc 2048
#define Dc 1024
#define Hc 16
#define HDc 64

// ---------------- scratch globals (allocation-free) ----------------
__device__ __half g_Q [Bc*Hc*Sc*HDc];           // Q fp16 (scaled by inv4*log2e)
__device__ __half g_K [Bc*Hc*Sc*HDc];           // K fp16 (scaled by inv4)
__device__ __half g_Vt[Bc*Hc*Sc*HDc];           // V^T [b,h,e,s], fp16
__device__ __half g_Z [Bc*Sc*Dc];               // Z fp16 ([s][k])
__device__ __half g_Wz[Dc*Dc];                  // Wz fp16 ([n][k])
__device__ __half g_W3[3*Hc*HDc*HDc];           // Wq/Wk/Wv fp16 (concat)
__device__ __half g_S[134217728];               // blocked unnormalized exp(score)
__device__ float g_isum[Bc*Hc*Sc];              // 1/rowsum

// ---------------- warp MMA helpers (base ISA: valid on sm_103 plain) ----------------
__device__ __forceinline__ void ldm4(uint32_t addr, uint32_t* r) {
    asm volatile("ldmatrix.sync.aligned.m8n8.x4.shared.b16 {%0,%1,%2,%3}, [%4];"
                 : "=r"(r[0]), "=r"(r[1]), "=r"(r[2]), "=r"(r[3]) : "r"(addr));
}
__device__ __forceinline__ void mma16816h(float* c, const uint32_t* a, uint32_t b0, uint32_t b1) {
    asm volatile("mma.sync.aligned.m16n8k16.row.col.f32.f16.f16.f32 "
                 "{%0,%1,%2,%3}, {%4,%5,%6,%7}, {%8,%9}, {%0,%1,%2,%3};"
                 : "+f"(c[0]), "+f"(c[1]), "+f"(c[2]), "+f"(c[3])
                 : "r"(a[0]), "r"(a[1]), "r"(a[2]), "r"(a[3]), "r"(b0), "r"(b1));
}
__device__ __forceinline__ void split_h(float x, __half& hi, __half& lo) {
    hi = __float2half_rn(x);
    lo = __float2half_rn(x - __half2float(hi));
}
__device__ __forceinline__ void cpasync16(uint32_t daddr, const void* gptr) {
    asm volatile("cp.async.cg.shared.global [%0], [%1], 16;" :: "r"(daddr), "l"(gptr));
}
#define CP_COMMIT() asm volatile("cp.async.commit_group;" ::: "memory")
#define CP_WAIT1()  asm volatile("cp.async.wait_group 1;" ::: "memory")
#define CP_WAIT0()  asm volatile("cp.async.wait_group 0;" ::: "memory")

// ---------------- W converts (single fp16) ----------------
__global__ __launch_bounds__(256) void w3_convert(
    const float* __restrict__ Wq, const float* __restrict__ Wk, const float* __restrict__ Wv)
{
    const float* src = (blockIdx.y == 0) ? Wq : (blockIdx.y == 1 ? Wk : Wv);
    int i = (blockIdx.x*256 + threadIdx.x)*4;
    int o = blockIdx.y*65536 + i;
    float4 v = *(const float4*)(src + i);
    __half2 a = __floats2half2_rn(v.x, v.y);
    __half2 b = __floats2half2_rn(v.z, v.w);
    *(uint32_t*)(g_W3 + o)     = *(uint32_t*)&a;
    *(uint32_t*)(g_W3 + o + 2) = *(uint32_t*)&b;
}
__global__ __launch_bounds__(256) void wz_convert(const float* __restrict__ Wz)
{
    int i = (blockIdx.x*256 + threadIdx.x)*4;
    float4 v = *(const float4*)(Wz + i);
    __half2 a = __floats2half2_rn(v.x, v.y);
    __half2 b = __floats2half2_rn(v.z, v.w);
    *(uint32_t*)(g_Wz + i)     = *(uint32_t*)&a;
    *(uint32_t*)(g_Wz + i + 2) = *(uint32_t*)&b;
}

// ---------------- QKV projection (warp HMMA, X hi/lo x W, 2-pass) ----------------
#define QP_XH 0
#define QP_XL 18432
#define QP_WH 36864
#define QP_XF 46080
#define SMEM_QP 80896

__global__ __launch_bounds__(256,1) void qkv_mma(
    const float* __restrict__ Xq, const float* __restrict__ Xk, const float* __restrict__ Xv)
{
    extern __shared__ char smem[];
    uint32_t sb = (uint32_t)__cvta_generic_to_shared(smem);
    int tid = threadIdx.x, wid = tid >> 5, lane = tid & 31;
    int s0 = blockIdx.x*128, h = blockIdx.y, b = blockIdx.z;
    size_t bh = (size_t)b*Hc + h;
    int tq = lane & 3;
    int row0 = 16*wid + (lane >> 2);

    const float inv4 = 0.35355339059327373f;
    const float l2e  = 1.4426950408889634f;
    const float* Xp[3] = {Xq, Xk, Xv};
    const float scl[3] = {inv4*l2e, inv4, 1.0f};

    for (int t = 0; t < 3; t++) {
        const float* X = Xp[t];
        for (int i = tid; i < 2048; i += 256) {
            int r = i >> 4, c = i & 15;
            cpasync16(sb + QP_XF + r*272 + c*16,
                      (const float4*)(X + ((size_t)(b*Sc + s0 + r))*Dc + h*64) + c);
        }
        int toff = t*65536 + h*4096;
        for (int i = tid; i < 512; i += 256) {
            int r = i >> 3, c = i & 7;
            cpasync16(sb + QP_WH + r*144 + c*16, (const float4*)(g_W3 + toff + r*64) + c);
        }
        CP_COMMIT(); CP_WAIT0();
        __syncthreads();

        const float* xf = (const float*)(smem + QP_XF);
        for (int p = tid; p < 4096; p += 256) {
            int r = p >> 5, dp = p & 31;
            float f0 = xf[r*68 + 2*dp], f1 = xf[r*68 + 2*dp + 1];
            __half h0,l0,h1,l1; split_h(f0,h0,l0); split_h(f1,h1,l1);
            __half2 hh = __halves2half2(h0,h1), ll = __halves2half2(l0,l1);
            *(uint32_t*)(smem + QP_XH + r*144 + 4*dp) = *(uint32_t*)&hh;
            *(uint32_t*)(smem + QP_XL + r*144 + 4*dp) = *(uint32_t*)&ll;
        }
        __syncthreads();

        uint32_t xh[4][4], xl[4][4];
        #pragma unroll
        for (int ks = 0; ks < 4; ks++) {
            uint32_t aaddr = sb + QP_XH + (16*wid + (lane & 15))*144 + ks*32 + ((lane >> 4) << 4);
            ldm4(aaddr, xh[ks]);
            ldm4(aaddr + (QP_XL - QP_XH), xl[ks]);
        }

        float s[32];
        #pragma unroll
        for (int i = 0; i < 32; i++) s[i] = 0.f;
        #pragma unroll
        for (int ks = 0; ks < 4; ks++) {
            #pragma unroll
            for (int nb2 = 0; nb2 < 4; nb2++) {
                uint32_t baddr = sb + QP_WH + (nb2*16 + (lane & 7) + ((lane >> 4) << 3))*144
                               + ks*32 + (((lane >> 3) & 1) << 4);
                uint32_t wh4[4];
                ldm4(baddr, wh4);
                mma16816h(s + 8*nb2,     xh[ks], wh4[0], wh4[1]);
                mma16816h(s + 8*nb2 + 4, xh[ks], wh4[2], wh4[3]);
                mma16816h(s + 8*nb2,     xl[ks], wh4[0], wh4[1]);
                mma16816h(s + 8*nb2 + 4, xl[ks], wh4[2], wh4[3]);
            }
        }

        if (t < 2) {
            __half* O = (t == 0 ? g_Q : g_K) + (bh*Sc + s0 + row0)*64;
            float sc = scl[t];
            #pragma unroll
            for (int nb = 0; nb < 8; nb++) {
                int col = nb*8 + 2*tq;
                __half2 a = __floats2half2_rn(s[4*nb+0]*sc, s[4*nb+1]*sc);
                __half2 c = __floats2half2_rn(s[4*nb+2]*sc, s[4*nb+3]*sc);
                *(uint32_t*)(O + col)          = *(uint32_t*)&a;
                *(uint32_t*)(O + 8*64 + col)   = *(uint32_t*)&c;
            }
        } else {
            __half* vb = (__half*)(smem + QP_XF);   // [64 e][136 s]
            #pragma unroll
            for (int nb = 0; nb < 8; nb++) {
                int col = nb*8 + 2*tq;
                vb[col*136 + row0]           = __float2half_rn(s[4*nb+0]);
                vb[(col+1)*136 + row0]       = __float2half_rn(s[4*nb+1]);
                vb[col*136 + row0 + 8]       = __float2half_rn(s[4*nb+2]);
                vb[(col+1)*136 + row0 + 8]   = __float2half_rn(s[4*nb+3]);
            }
            __syncthreads();
            __half* Ov = g_Vt + bh*(size_t)64*Sc;
            for (int u = tid; u < 4096; u += 256) {
                int e = u >> 6, sc2 = u & 63;
                uint32_t v = *(uint32_t*)&vb[e*136 + 2*sc2];
                *(uint32_t*)(Ov + (size_t)e*Sc + s0 + 2*sc2) = v;
            }
        }
        __syncthreads();
    }
}

// ---------------- flash attention (fp16 HMMA, M=32/warp, blocked g_S stores) -----------
// grid (S/256, H, B), 256 threads, 36KB dyn smem, 2 blocks/SM.
#define BUF_SZ  18432
#define SMEM_FL 36864

__device__ __forceinline__ void stage_k_async(uint32_t dst, const float4* gsrc, int tid) {
    for (int i = tid; i < 512; i += 256) {
        int r = i >> 3, c = i & 7;
        cpasync16(dst + r*144 + c*16, gsrc + i);
    }
}
__device__ __forceinline__ void stage_v_async(uint32_t dst, const float4* gv, int kb, int tid) {
    for (int i = tid; i < 512; i += 256) {
        int e = i >> 3, c = i & 7;
        cpasync16(dst + e*144 + c*16, gv + e*256 + kb*8 + c);
    }
}
__device__ __forceinline__ void issue_tile(uint32_t buf, size_t bh, int kb,
                                           const float4* gv, int tid) {
    const float4* kh = (const float4*)g_K + ((bh*Sc + (size_t)kb*64) << 3);
    stage_k_async(buf,        kh, tid);
    stage_v_async(buf + 9216, gv, kb, tid);
    CP_COMMIT();
}

__global__ __launch_bounds__(256,2) void flash_attn()
{
    extern __shared__ char smem[];
    uint32_t sb = (uint32_t)__cvta_generic_to_shared(smem);
    int tid = threadIdx.x, wid = tid >> 5, lane = tid & 31;
    int q0 = blockIdx.x*256, h = blockIdx.y, b = blockIdx.z;
    size_t bh = (size_t)b*Hc + h;
    int t = lane & 3;
    int row0 = 32*wid + (lane >> 2);   // rows row0, +8, +16, +24

    const float4* gv = (const float4*)(g_Vt + bh*(size_t)64*Sc);

    // --- prologue: Q (256 rows) into full smem region, load fragments ---
    {
        const float4* gq = (const float4*)g_Q + ((bh*Sc + q0) << 3);
        for (int i = tid; i < 2048; i += 256) {
            int r = i >> 3, c = i & 7;
            cpasync16(sb + r*144 + c*16, gq + i);
        }
    }
    CP_COMMIT(); CP_WAIT0();
    __syncthreads();

    uint32_t qf[2][4][4];
    #pragma unroll
    for (int tl = 0; tl < 2; tl++)
        #pragma unroll
        for (int ks = 0; ks < 4; ks++) {
            uint32_t aaddr = sb + (32*wid + tl*16 + (lane & 15))*144 + ks*32 + ((lane >> 4) << 4);
            ldm4(aaddr, qf[tl][ks]);
        }
    __syncthreads();   // Q reads done before overwrite

    issue_tile(sb,          bh, 0, gv, tid);
    issue_tile(sb + BUF_SZ, bh, 1, gv, tid);

    float z0[32], z1[32];
    #pragma unroll
    for (int i = 0; i < 32; i++) { z0[i] = 0.f; z1[i] = 0.f; }
    float rs[4] = {0.f, 0.f, 0.f, 0.f};
    uint32_t* gSu = (uint32_t*)g_S;
    size_t warpbase = (((bh*8 + blockIdx.x)*8 + wid)*128)*256;   // uint32 units

    for (int kb = 0; kb < Sc/64; kb++) {
        if (kb < Sc/64 - 1) { CP_WAIT1(); } else { CP_WAIT0(); }
        __syncthreads();
        uint32_t buf = sb + (kb & 1)*BUF_SZ;

        // ---- per 16-key chunk: QK -> epilogue -> PV ----
        #pragma unroll
        for (int m = 0; m < 4; m++) {
            float s0[8], s1[8];
            #pragma unroll
            for (int i = 0; i < 8; i++) { s0[i] = 0.f; s1[i] = 0.f; }
            #pragma unroll
            for (int ks = 0; ks < 4; ks++) {
                uint32_t baddr = buf + (m*16 + (lane & 7) + ((lane >> 4) << 3))*144
                               + ks*32 + (((lane >> 3) & 1) << 4);
                uint32_t bhf[4];
                ldm4(baddr, bhf);
                mma16816h(s0,     qf[0][ks], bhf[0], bhf[1]);
                mma16816h(s0 + 4, qf[0][ks], bhf[2], bhf[3]);
                mma16816h(s1,     qf[1][ks], bhf[0], bhf[1]);
                mma16816h(s1 + 4, qf[1][ks], bhf[2], bhf[3]);
            }

            // tile 0 (rows row0, row0+8)
            float a0 = exp2f(s0[0]), a1 = exp2f(s0[1]);
            float a2 = exp2f(s0[2]), a3 = exp2f(s0[3]);
            float b0 = exp2f(s0[4]), b1 = exp2f(s0[5]);
            float b2 = exp2f(s0[6]), b3 = exp2f(s0[7]);
            rs[0] += a0 + a1 + b0 + b1;
            rs[1] += a2 + a3 + b2 + b3;
            uint32_t af0[4];
            __half2 p0 = __floats2half2_rn(a0, a1);
            __half2 p1 = __floats2half2_rn(a2, a3);
            __half2 p2 = __floats2half2_rn(b0, b1);
            __half2 p3 = __floats2half2_rn(b2, b3);
            af0[0] = *(uint32_t*)&p0; af0[1] = *(uint32_t*)&p1;
            af0[2] = *(uint32_t*)&p2; af0[3] = *(uint32_t*)&p3;
            // tile 1 (rows row0+16, row0+24)
            float c0 = exp2f(s1[0]), c1 = exp2f(s1[1]);
            float c2 = exp2f(s1[2]), c3 = exp2f(s1[3]);
            float d0 = exp2f(s1[4]), d1 = exp2f(s1[5]);
            float d2 = exp2f(s1[6]), d3 = exp2f(s1[7]);
            rs[2] += c0 + c1 + d0 + d1;
            rs[3] += c2 + c3 + d2 + d3;
            uint32_t af1[4];
            __half2 q0h = __floats2half2_rn(c0, c1);
            __half2 q1h = __floats2half2_rn(c2, c3);
            __half2 q2h = __floats2half2_rn(d0, d1);
            __half2 q3h = __floats2half2_rn(d2, d3);
            af1[0] = *(uint32_t*)&q0h; af1[1] = *(uint32_t*)&q1h;
            af1[2] = *(uint32_t*)&q2h; af1[3] = *(uint32_t*)&q3h;

            // blocked coalesced g_S store: af0 block then af1 block, lane-major
            size_t cbase = warpbase + (size_t)(kb*4 + m)*256;
            *(uint4*)(gSu + cbase + lane*4)       = make_uint4(af0[0],af0[1],af0[2],af0[3]);
            *(uint4*)(gSu + cbase + 128 + lane*4) = make_uint4(af1[0],af1[1],af1[2],af1[3]);

            #pragma unroll
            for (int nb2 = 0; nb2 < 4; nb2++) {
                uint32_t vaddr = buf + 9216 + (nb2*16 + (lane & 7) + ((lane >> 4) << 3))*144
                               + m*32 + (((lane >> 3) & 1) << 4);
                uint32_t bhf[4];
                ldm4(vaddr, bhf);
                mma16816h(z0 + 8*nb2,     af0, bhf[0], bhf[1]);
                mma16816h(z0 + 8*nb2 + 4, af0, bhf[2], bhf[3]);
                mma16816h(z1 + 8*nb2,     af1, bhf[0], bhf[1]);
                mma16816h(z1 + 8*nb2 + 4, af1, bhf[2], bhf[3]);
            }
        }
        __syncthreads();   // all warps done with this buffer
        if (kb + 2 < Sc/64)
            issue_tile(sb + (kb & 1)*BUF_SZ, bh, kb + 2, gv, tid);
    }

    // rowsum reduce within quad
    #pragma unroll
    for (int r = 0; r < 4; r++)
        #pragma unroll
        for (int o = 1; o <= 2; o <<= 1)
            rs[r] += __shfl_xor_sync(0xffffffffu, rs[r], o);
    float inv0 = 1.f/rs[0], inv1 = 1.f/rs[1], inv2 = 1.f/rs[2], inv3 = 1.f/rs[3];
    __half* zo = g_Z + ((size_t)b*Sc + q0 + row0)*Dc + h*64;
    #pragma unroll
    for (int nb = 0; nb < 8; nb++) {
        int col = nb*8 + 2*t;
        __half2 a = __floats2half2_rn(z0[nb*4+0]*inv0, z0[nb*4+1]*inv0);
        __half2 c = __floats2half2_rn(z0[nb*4+2]*inv1, z0[nb*4+3]*inv1);
        __half2 e = __floats2half2_rn(z1[nb*4+0]*inv2, z1[nb*4+1]*inv2);
        __half2 f = __floats2half2_rn(z1[nb*4+2]*inv3, z1[nb*4+3]*inv3);
        *(uint32_t*)(zo + col)                    = *(uint32_t*)&a;
        *(uint32_t*)(zo + (size_t)8*Dc + col)     = *(uint32_t*)&c;
        *(uint32_t*)(zo + (size_t)16*Dc + col)    = *(uint32_t*)&e;
        *(uint32_t*)(zo + (size_t)24*Dc + col)    = *(uint32_t*)&f;
    }
    if (t == 0) {
        g_isum[bh*Sc + q0 + row0]      = inv0;
        g_isum[bh*Sc + q0 + row0 + 8]  = inv1;
        g_isum[bh*Sc + q0 + row0 + 16] = inv2;
        g_isum[bh*Sc + q0 + row0 + 24] = inv3;
    }
}

// ---------------- attn_mean over blocked g_S layout ----------------
// grid (64, B): block = (bxf, wid) = one flash-warp's 32 q-rows.
__global__ __launch_bounds__(256) void attn_mean_kernel(float* __restrict__ am)
{
    __shared__ float wsum[512];   // [h][32 rows], premultiplied by 1/H
    int bx2 = blockIdx.x, b = blockIdx.y;
    int bxf = bx2 >> 3, wid = bx2 & 7;
    int Q0 = bxf*256 + wid*32;
    int tid = threadIdx.x;
    for (int i2 = tid; i2 < 512; i2 += 256) {
        int h = i2 >> 5, r = i2 & 31;
        wsum[i2] = g_isum[((size_t)b*Hc + h)*Sc + Q0 + r] * (1.0f/Hc);
    }
    __syncthreads();

    int k = tid & 63, cq = tid >> 6;       // uint4 index within chunk, chunk-quarter
    int part = k >> 5, lane = k & 31;
    int g = lane >> 2, t = lane & 3;
    int r0 = g + part*16, r1 = r0 + 8;
    const uint4* gS4 = (const uint4*)g_S;
    const size_t hstride = (size_t)8*8*128*64;             // uint4 per h
    size_t base0 = ((size_t)(b*128 + bxf)*8 + wid)*8192;   // uint4 units (h=0)
    float* am0 = am + ((size_t)b*Sc + Q0 + r0)*Sc;
    float* am1 = am + ((size_t)b*Sc + Q0 + r1)*Sc;

    for (int cb = 0; cb < 32; cb++) {
        float a00x=0,a00y=0,a10x=0,a10y=0,a01x=0,a01y=0,a11x=0,a11y=0;
        size_t addr = base0 + (size_t)(cb*4 + cq)*64 + k;
        #pragma unroll 4
        for (int h = 0; h < Hc; h++) {
            uint4 v = gS4[addr + (size_t)h*hstride];
            float w0 = wsum[h*32 + r0], w1 = wsum[h*32 + r1];
            float2 f0 = __half22float2(*(__half2*)&v.x);
            float2 f1 = __half22float2(*(__half2*)&v.y);
            float2 f2 = __half22float2(*(__half2*)&v.z);
            float2 f3 = __half22float2(*(__half2*)&v.w);
            a00x += f0.x*w0; a00y += f0.y*w0;
            a10x += f1.x*w1; a10y += f1.y*w1;
            a01x += f2.x*w0; a01y += f2.y*w0;
            a11x += f3.x*w1; a11y += f3.y*w1;
        }
        int colbase = cb*64 + cq*16;
        *(float2*)(am0 + colbase + 2*t)     = make_float2(a00x, a00y);
        *(float2*)(am1 + colbase + 2*t)     = make_float2(a10x, a10y);
        *(float2*)(am0 + colbase + 8 + 2*t) = make_float2(a01x, a01y);
        *(float2*)(am1 + colbase + 8 + 2*t) = make_float2(a11x, a11y);
    }
}

// ---------------- Output projection (fp16 HMMA, single pass Z x W) ----------------
#define SM_Z 0
#define SM_W 18432
#define SMEM_OP 36864

__device__ __forceinline__ void stage_op(char* smem, int off, const float4* gs,
                                         int base_row, int kc, int tid) {
    #pragma unroll
    for (int it = 0; it < 4; it++) {
        int i = tid + it*256;
        int r = i >> 3, c = i & 7;
        *(float4*)(smem + off + r*144 + c*16) = gs[(size_t)(base_row + r)*128 + kc*8 + c];
    }
}

__global__ __launch_bounds__(256,1) void out_proj_mma(
    const float* __restrict__ bz, float* __restrict__ out)
{
    extern __shared__ char smem[];
    uint32_t sb = (uint32_t)__cvta_generic_to_shared(smem);
    int tid = threadIdx.x, wid = tid >> 5, lane = tid & 31;
    int n0 = blockIdx.x*128, s0 = blockIdx.y*128;
    int t = lane & 3;
    int row0 = 16*wid + (lane >> 2);

    const float4* gz = (const float4*)g_Z;
    const float4* gw = (const float4*)g_Wz;

    float s[64];
    #pragma unroll
    for (int i = 0; i < 64; i++) s[i] = 0.f;

    for (int kc = 0; kc < 16; kc++) {
        if (kc) __syncthreads();
        stage_op(smem, SM_Z, gz, s0, kc, tid);
        stage_op(smem, SM_W, gw, n0, kc, tid);
        __syncthreads();

        #pragma unroll
        for (int ks = 0; ks < 4; ks++) {
            uint32_t aaddr = sb + SM_Z + (16*wid + (lane & 15))*144 + ks*32 + ((lane >> 4) << 4);
            uint32_t ah[4];
            ldm4(aaddr, ah);
            #pragma unroll
            for (int nb2 = 0; nb2 < 8; nb2++) {
                uint32_t baddr = sb + SM_W + (nb2*16 + (lane & 7) + ((lane >> 4) << 3))*144
                               + ks*32 + (((lane >> 3) & 1) << 4);
                uint32_t bhf[4];
                ldm4(baddr, bhf);
                mma16816h(s + (2*nb2)*4,   ah, bhf[0], bhf[1]);
                mma16816h(s + (2*nb2+1)*4, ah, bhf[2], bhf[3]);
            }
        }
    }

    float* o0 = out + (size_t)(s0 + row0)*Dc + n0;
    float* o1 = o0 + (size_t)8*Dc;
    #pragma unroll
    for (int nb = 0; nb < 16; nb++) {
        int col = nb*8 + 2*t;
        float b0 = bz[n0 + col], b1 = bz[n0 + col + 1];
        *(float2*)(o0 + col) = make_float2(s[nb*4+0] + b0, s[nb*4+1] + b1);
        *(float2*)(o1 + col) = make_float2(s[nb*4+2] + b0, s[nb*4+3] + b1);
    }
}

extern "C" void kernel_launch(void* const* d_in, const int* in_sizes, int n_in,
                              void* d_out, int out_size)
{
    const float* Xq = (const float*)d_in[0];
    const float* Xk = (const float*)d_in[1];
    const float* Xv = (const float*)d_in[2];
    const float* Wq = (const float*)d_in[3];
    const float* Wk = (const float*)d_in[4];
    const float* Wv = (const float*)d_in[5];
    const float* Wz = (const float*)d_in[6];
    const float* bz = (const float*)d_in[7];
    float* out  = (float*)d_out;
    float* attn = out + (size_t)Bc*Sc*Dc;   // out first, then attn_mean

    cudaFuncSetAttribute((const void*)qkv_mma,
                         cudaFuncAttributeMaxDynamicSharedMemorySize, SMEM_QP);
    cudaFuncSetAttribute((const void*)flash_attn,
                         cudaFuncAttributeMaxDynamicSharedMemorySize, SMEM_FL);
    cudaFuncSetAttribute((const void*)out_proj_mma,
                         cudaFuncAttributeMaxDynamicSharedMemorySize, SMEM_OP);

    w3_convert<<<dim3(64, 3), 256>>>(Wq, Wk, Wv);
    wz_convert<<<Dc*Dc/1024, 256>>>(Wz);
    qkv_mma<<<dim3(Sc/128, Hc, Bc), 256, SMEM_QP>>>(Xq, Xk, Xv);
    flash_attn<<<dim3(Sc/256, Hc, Bc), 256, SMEM_FL>>>();
    attn_mean_kernel<<<dim3(64, Bc), 256>>>(attn);
    out_proj_mma<<<dim3(Dc/128, (Bc*Sc)/128), 256, SMEM_OP>>>(bz, out);
}

// round 17
// speedup vs baseline: 1.3820x; 1.3820x over previous
#include <cuda_runtime.h>
#include <cuda_bf16.h>
#include <cuda_fp16.h>
#include <cstdint>

#define Bc 2
#define Sc 2048
#define Dc 1024
#define Hc 16
#define HDc 64

// ---------------- scratch globals (allocation-free) ----------------
__device__ __half g_Q [Bc*Hc*Sc*HDc];           // Q fp16 (scaled by inv4*log2e)
__device__ __half g_K [Bc*Hc*Sc*HDc];           // K fp16 (scaled by inv4)
__device__ __half g_Vt[Bc*Hc*Sc*HDc];           // V^T [b,h,e,s], fp16
__device__ __half g_Z [Bc*Sc*Dc];               // Z fp16 ([s][k])
__device__ __half g_Wz[Dc*Dc];                  // Wz fp16 ([n][k])
__device__ __half g_W3[3*Hc*HDc*HDc];           // Wq/Wk/Wv fp16 (concat)
__device__ __half g_S[134217728];               // blocked unnormalized exp(score)
__device__ float g_isum[Bc*Hc*Sc];              // 1/rowsum

// ---------------- warp MMA helpers (base ISA: valid on sm_103 plain) ----------------
__device__ __forceinline__ void ldm4(uint32_t addr, uint32_t* r) {
    asm volatile("ldmatrix.sync.aligned.m8n8.x4.shared.b16 {%0,%1,%2,%3}, [%4];"
                 : "=r"(r[0]), "=r"(r[1]), "=r"(r[2]), "=r"(r[3]) : "r"(addr));
}
__device__ __forceinline__ void mma16816h(float* c, const uint32_t* a, uint32_t b0, uint32_t b1) {
    asm volatile("mma.sync.aligned.m16n8k16.row.col.f32.f16.f16.f32 "
                 "{%0,%1,%2,%3}, {%4,%5,%6,%7}, {%8,%9}, {%0,%1,%2,%3};"
                 : "+f"(c[0]), "+f"(c[1]), "+f"(c[2]), "+f"(c[3])
                 : "r"(a[0]), "r"(a[1]), "r"(a[2]), "r"(a[3]), "r"(b0), "r"(b1));
}
__device__ __forceinline__ void split_h(float x, __half& hi, __half& lo) {
    hi = __float2half_rn(x);
    lo = __float2half_rn(x - __half2float(hi));
}
__device__ __forceinline__ void cpasync16(uint32_t daddr, const void* gptr) {
    asm volatile("cp.async.cg.shared.global [%0], [%1], 16;" :: "r"(daddr), "l"(gptr));
}
#define CP_COMMIT() asm volatile("cp.async.commit_group;" ::: "memory")
#define CP_WAIT1()  asm volatile("cp.async.wait_group 1;" ::: "memory")
#define CP_WAIT0()  asm volatile("cp.async.wait_group 0;" ::: "memory")

// ---------------- W converts (single fp16) ----------------
__global__ __launch_bounds__(256) void w3_convert(
    const float* __restrict__ Wq, const float* __restrict__ Wk, const float* __restrict__ Wv)
{
    const float* src = (blockIdx.y == 0) ? Wq : (blockIdx.y == 1 ? Wk : Wv);
    int i = (blockIdx.x*256 + threadIdx.x)*4;
    int o = blockIdx.y*65536 + i;
    float4 v = *(const float4*)(src + i);
    __half2 a = __floats2half2_rn(v.x, v.y);
    __half2 b = __floats2half2_rn(v.z, v.w);
    *(uint32_t*)(g_W3 + o)     = *(uint32_t*)&a;
    *(uint32_t*)(g_W3 + o + 2) = *(uint32_t*)&b;
}
__global__ __launch_bounds__(256) void wz_convert(const float* __restrict__ Wz)
{
    int i = (blockIdx.x*256 + threadIdx.x)*4;
    float4 v = *(const float4*)(Wz + i);
    __half2 a = __floats2half2_rn(v.x, v.y);
    __half2 b = __floats2half2_rn(v.z, v.w);
    *(uint32_t*)(g_Wz + i)     = *(uint32_t*)&a;
    *(uint32_t*)(g_Wz + i + 2) = *(uint32_t*)&b;
}

// ---------------- QKV projection (warp HMMA, X hi/lo x W, 2-pass) ----------------
#define QP_XH 0
#define QP_XL 18432
#define QP_WH 36864
#define QP_XF 46080
#define SMEM_QP 80896

__global__ __launch_bounds__(256,1) void qkv_mma(
    const float* __restrict__ Xq, const float* __restrict__ Xk, const float* __restrict__ Xv)
{
    extern __shared__ char smem[];
    uint32_t sb = (uint32_t)__cvta_generic_to_shared(smem);
    int tid = threadIdx.x, wid = tid >> 5, lane = tid & 31;
    int s0 = blockIdx.x*128, h = blockIdx.y, b = blockIdx.z;
    size_t bh = (size_t)b*Hc + h;
    int tq = lane & 3;
    int row0 = 16*wid + (lane >> 2);

    const float inv4 = 0.35355339059327373f;
    const float l2e  = 1.4426950408889634f;
    const float* Xp[3] = {Xq, Xk, Xv};
    const float scl[3] = {inv4*l2e, inv4, 1.0f};

    for (int t = 0; t < 3; t++) {
        const float* X = Xp[t];
        for (int i = tid; i < 2048; i += 256) {
            int r = i >> 4, c = i & 15;
            cpasync16(sb + QP_XF + r*272 + c*16,
                      (const float4*)(X + ((size_t)(b*Sc + s0 + r))*Dc + h*64) + c);
        }
        int toff = t*65536 + h*4096;
        for (int i = tid; i < 512; i += 256) {
            int r = i >> 3, c = i & 7;
            cpasync16(sb + QP_WH + r*144 + c*16, (const float4*)(g_W3 + toff + r*64) + c);
        }
        CP_COMMIT(); CP_WAIT0();
        __syncthreads();

        const float* xf = (const float*)(smem + QP_XF);
        for (int p = tid; p < 4096; p += 256) {
            int r = p >> 5, dp = p & 31;
            float f0 = xf[r*68 + 2*dp], f1 = xf[r*68 + 2*dp + 1];
            __half h0,l0,h1,l1; split_h(f0,h0,l0); split_h(f1,h1,l1);
            __half2 hh = __halves2half2(h0,h1), ll = __halves2half2(l0,l1);
            *(uint32_t*)(smem + QP_XH + r*144 + 4*dp) = *(uint32_t*)&hh;
            *(uint32_t*)(smem + QP_XL + r*144 + 4*dp) = *(uint32_t*)&ll;
        }
        __syncthreads();

        uint32_t xh[4][4], xl[4][4];
        #pragma unroll
        for (int ks = 0; ks < 4; ks++) {
            uint32_t aaddr = sb + QP_XH + (16*wid + (lane & 15))*144 + ks*32 + ((lane >> 4) << 4);
            ldm4(aaddr, xh[ks]);
            ldm4(aaddr + (QP_XL - QP_XH), xl[ks]);
        }

        float s[32];
        #pragma unroll
        for (int i = 0; i < 32; i++) s[i] = 0.f;
        #pragma unroll
        for (int ks = 0; ks < 4; ks++) {
            #pragma unroll
            for (int nb2 = 0; nb2 < 4; nb2++) {
                uint32_t baddr = sb + QP_WH + (nb2*16 + (lane & 7) + ((lane >> 4) << 3))*144
                               + ks*32 + (((lane >> 3) & 1) << 4);
                uint32_t wh4[4];
                ldm4(baddr, wh4);
                mma16816h(s + 8*nb2,     xh[ks], wh4[0], wh4[1]);
                mma16816h(s + 8*nb2 + 4, xh[ks], wh4[2], wh4[3]);
                mma16816h(s + 8*nb2,     xl[ks], wh4[0], wh4[1]);
                mma16816h(s + 8*nb2 + 4, xl[ks], wh4[2], wh4[3]);
            }
        }

        if (t < 2) {
            __half* O = (t == 0 ? g_Q : g_K) + (bh*Sc + s0 + row0)*64;
            float sc = scl[t];
            #pragma unroll
            for (int nb = 0; nb < 8; nb++) {
                int col = nb*8 + 2*tq;
                __half2 a = __floats2half2_rn(s[4*nb+0]*sc, s[4*nb+1]*sc);
                __half2 c = __floats2half2_rn(s[4*nb+2]*sc, s[4*nb+3]*sc);
                *(uint32_t*)(O + col)          = *(uint32_t*)&a;
                *(uint32_t*)(O + 8*64 + col)   = *(uint32_t*)&c;
            }
        } else {
            __half* vb = (__half*)(smem + QP_XF);   // [64 e][136 s]
            #pragma unroll
            for (int nb = 0; nb < 8; nb++) {
                int col = nb*8 + 2*tq;
                vb[col*136 + row0]           = __float2half_rn(s[4*nb+0]);
                vb[(col+1)*136 + row0]       = __float2half_rn(s[4*nb+1]);
                vb[col*136 + row0 + 8]       = __float2half_rn(s[4*nb+2]);
                vb[(col+1)*136 + row0 + 8]   = __float2half_rn(s[4*nb+3]);
            }
            __syncthreads();
            __half* Ov = g_Vt + bh*(size_t)64*Sc;
            for (int u = tid; u < 4096; u += 256) {
                int e = u >> 6, sc2 = u & 63;
                uint32_t v = *(uint32_t*)&vb[e*136 + 2*sc2];
                *(uint32_t*)(Ov + (size_t)e*Sc + s0 + 2*sc2) = v;
            }
        }
        __syncthreads();
    }
}

// ---------------- flash attention (fp16 HMMA, M=32/warp, blocked g_S stores) -----------
// grid (S/256, H, B), 256 threads, 36KB dyn smem, 2 blocks/SM.
#define BUF_SZ  18432
#define SMEM_FL 36864

__device__ __forceinline__ void stage_k_async(uint32_t dst, const float4* gsrc, int tid) {
    for (int i = tid; i < 512; i += 256) {
        int r = i >> 3, c = i & 7;
        cpasync16(dst + r*144 + c*16, gsrc + i);
    }
}
__device__ __forceinline__ void stage_v_async(uint32_t dst, const float4* gv, int kb, int tid) {
    for (int i = tid; i < 512; i += 256) {
        int e = i >> 3, c = i & 7;
        cpasync16(dst + e*144 + c*16, gv + e*256 + kb*8 + c);
    }
}
__device__ __forceinline__ void issue_tile(uint32_t buf, size_t bh, int kb,
                                           const float4* gv, int tid) {
    const float4* kh = (const float4*)g_K + ((bh*Sc + (size_t)kb*64) << 3);
    stage_k_async(buf,        kh, tid);
    stage_v_async(buf + 9216, gv, kb, tid);
    CP_COMMIT();
}

__global__ __launch_bounds__(256,2) void flash_attn()
{
    extern __shared__ char smem[];
    uint32_t sb = (uint32_t)__cvta_generic_to_shared(smem);
    int tid = threadIdx.x, wid = tid >> 5, lane = tid & 31;
    int q0 = blockIdx.x*256, h = blockIdx.y, b = blockIdx.z;
    size_t bh = (size_t)b*Hc + h;
    int t = lane & 3;
    int row0 = 32*wid + (lane >> 2);   // rows row0, +8, +16, +24

    const float4* gv = (const float4*)(g_Vt + bh*(size_t)64*Sc);

    // --- prologue: Q (256 rows) into full smem region, load fragments ---
    {
        const float4* gq = (const float4*)g_Q + ((bh*Sc + q0) << 3);
        for (int i = tid; i < 2048; i += 256) {
            int r = i >> 3, c = i & 7;
            cpasync16(sb + r*144 + c*16, gq + i);
        }
    }
    CP_COMMIT(); CP_WAIT0();
    __syncthreads();

    uint32_t qf[2][4][4];
    #pragma unroll
    for (int tl = 0; tl < 2; tl++)
        #pragma unroll
        for (int ks = 0; ks < 4; ks++) {
            uint32_t aaddr = sb + (32*wid + tl*16 + (lane & 15))*144 + ks*32 + ((lane >> 4) << 4);
            ldm4(aaddr, qf[tl][ks]);
        }
    __syncthreads();   // Q reads done before overwrite

    issue_tile(sb,          bh, 0, gv, tid);
    issue_tile(sb + BUF_SZ, bh, 1, gv, tid);

    float z0[32], z1[32];
    #pragma unroll
    for (int i = 0; i < 32; i++) { z0[i] = 0.f; z1[i] = 0.f; }
    float rs[4] = {0.f, 0.f, 0.f, 0.f};
    uint32_t* gSu = (uint32_t*)g_S;
    size_t warpbase = (((bh*8 + blockIdx.x)*8 + wid)*128)*256;   // uint32 units

    for (int kb = 0; kb < Sc/64; kb++) {
        if (kb < Sc/64 - 1) { CP_WAIT1(); } else { CP_WAIT0(); }
        __syncthreads();
        uint32_t buf = sb + (kb & 1)*BUF_SZ;

        // ---- per 16-key chunk: QK -> epilogue -> PV ----
        #pragma unroll
        for (int m = 0; m < 4; m++) {
            float s0[8], s1[8];
            #pragma unroll
            for (int i = 0; i < 8; i++) { s0[i] = 0.f; s1[i] = 0.f; }
            #pragma unroll
            for (int ks = 0; ks < 4; ks++) {
                uint32_t baddr = buf + (m*16 + (lane & 7) + ((lane >> 4) << 3))*144
                               + ks*32 + (((lane >> 3) & 1) << 4);
                uint32_t bhf[4];
                ldm4(baddr, bhf);
                mma16816h(s0,     qf[0][ks], bhf[0], bhf[1]);
                mma16816h(s0 + 4, qf[0][ks], bhf[2], bhf[3]);
                mma16816h(s1,     qf[1][ks], bhf[0], bhf[1]);
                mma16816h(s1 + 4, qf[1][ks], bhf[2], bhf[3]);
            }

            // tile 0 (rows row0, row0+8)
            float a0 = exp2f(s0[0]), a1 = exp2f(s0[1]);
            float a2 = exp2f(s0[2]), a3 = exp2f(s0[3]);
            float b0 = exp2f(s0[4]), b1 = exp2f(s0[5]);
            float b2 = exp2f(s0[6]), b3 = exp2f(s0[7]);
            rs[0] += a0 + a1 + b0 + b1;
            rs[1] += a2 + a3 + b2 + b3;
            uint32_t af0[4];
            __half2 p0 = __floats2half2_rn(a0, a1);
            __half2 p1 = __floats2half2_rn(a2, a3);
            __half2 p2 = __floats2half2_rn(b0, b1);
            __half2 p3 = __floats2half2_rn(b2, b3);
            af0[0] = *(uint32_t*)&p0; af0[1] = *(uint32_t*)&p1;
            af0[2] = *(uint32_t*)&p2; af0[3] = *(uint32_t*)&p3;
            // tile 1 (rows row0+16, row0+24)
            float c0 = exp2f(s1[0]), c1 = exp2f(s1[1]);
            float c2 = exp2f(s1[2]), c3 = exp2f(s1[3]);
            float d0 = exp2f(s1[4]), d1 = exp2f(s1[5]);
            float d2 = exp2f(s1[6]), d3 = exp2f(s1[7]);
            rs[2] += c0 + c1 + d0 + d1;
            rs[3] += c2 + c3 + d2 + d3;
            uint32_t af1[4];
            __half2 q0h = __floats2half2_rn(c0, c1);
            __half2 q1h = __floats2half2_rn(c2, c3);
            __half2 q2h = __floats2half2_rn(d0, d1);
            __half2 q3h = __floats2half2_rn(d2, d3);
            af1[0] = *(uint32_t*)&q0h; af1[1] = *(uint32_t*)&q1h;
            af1[2] = *(uint32_t*)&q2h; af1[3] = *(uint32_t*)&q3h;

            // blocked coalesced g_S store: af0 block then af1 block, lane-major
            size_t cbase = warpbase + (size_t)(kb*4 + m)*256;
            *(uint4*)(gSu + cbase + lane*4)       = make_uint4(af0[0],af0[1],af0[2],af0[3]);
            *(uint4*)(gSu + cbase + 128 + lane*4) = make_uint4(af1[0],af1[1],af1[2],af1[3]);

            #pragma unroll
            for (int nb2 = 0; nb2 < 4; nb2++) {
                uint32_t vaddr = buf + 9216 + (nb2*16 + (lane & 7) + ((lane >> 4) << 3))*144
                               + m*32 + (((lane >> 3) & 1) << 4);
                uint32_t bhf[4];
                ldm4(vaddr, bhf);
                mma16816h(z0 + 8*nb2,     af0, bhf[0], bhf[1]);
                mma16816h(z0 + 8*nb2 + 4, af0, bhf[2], bhf[3]);
                mma16816h(z1 + 8*nb2,     af1, bhf[0], bhf[1]);
                mma16816h(z1 + 8*nb2 + 4, af1, bhf[2], bhf[3]);
            }
        }
        __syncthreads();   // all warps done with this buffer
        if (kb + 2 < Sc/64)
            issue_tile(sb + (kb & 1)*BUF_SZ, bh, kb + 2, gv, tid);
    }

    // rowsum reduce within quad
    #pragma unroll
    for (int r = 0; r < 4; r++)
        #pragma unroll
        for (int o = 1; o <= 2; o <<= 1)
            rs[r] += __shfl_xor_sync(0xffffffffu, rs[r], o);
    float inv0 = 1.f/rs[0], inv1 = 1.f/rs[1], inv2 = 1.f/rs[2], inv3 = 1.f/rs[3];
    __half* zo = g_Z + ((size_t)b*Sc + q0 + row0)*Dc + h*64;
    #pragma unroll
    for (int nb = 0; nb < 8; nb++) {
        int col = nb*8 + 2*t;
        __half2 a = __floats2half2_rn(z0[nb*4+0]*inv0, z0[nb*4+1]*inv0);
        __half2 c = __floats2half2_rn(z0[nb*4+2]*inv1, z0[nb*4+3]*inv1);
        __half2 e = __floats2half2_rn(z1[nb*4+0]*inv2, z1[nb*4+1]*inv2);
        __half2 f = __floats2half2_rn(z1[nb*4+2]*inv3, z1[nb*4+3]*inv3);
        *(uint32_t*)(zo + col)                    = *(uint32_t*)&a;
        *(uint32_t*)(zo + (size_t)8*Dc + col)     = *(uint32_t*)&c;
        *(uint32_t*)(zo + (size_t)16*Dc + col)    = *(uint32_t*)&e;
        *(uint32_t*)(zo + (size_t)24*Dc + col)    = *(uint32_t*)&f;
    }
    if (t == 0) {
        g_isum[bh*Sc + q0 + row0]      = inv0;
        g_isum[bh*Sc + q0 + row0 + 8]  = inv1;
        g_isum[bh*Sc + q0 + row0 + 16] = inv2;
        g_isum[bh*Sc + q0 + row0 + 24] = inv3;
    }
}

// ---------------- attn_mean over blocked g_S layout (chunk-sliced grid) ----------------
// grid (512, B): blockIdx.x = (bxf*8 + wid)*8 + slice; each block does 4 of 32 chunk-blocks.
__global__ __launch_bounds__(256) void attn_mean_kernel(float* __restrict__ am)
{
    __shared__ float wsum[512];   // [h][32 rows], premultiplied by 1/H
    int bx2 = blockIdx.x, b = blockIdx.y;
    int slice = bx2 & 7;
    int bxw = bx2 >> 3;            // 0..63
    int bxf = bxw >> 3, wid = bxw & 7;
    int Q0 = bxf*256 + wid*32;
    int tid = threadIdx.x;
    for (int i2 = tid; i2 < 512; i2 += 256) {
        int h = i2 >> 5, r = i2 & 31;
        wsum[i2] = g_isum[((size_t)b*Hc + h)*Sc + Q0 + r] * (1.0f/Hc);
    }
    __syncthreads();

    int k = tid & 63, cq = tid >> 6;       // uint4 index within chunk, chunk-quarter
    int part = k >> 5, lane = k & 31;
    int g = lane >> 2, t = lane & 3;
    int r0 = g + part*16, r1 = r0 + 8;
    const uint4* gS4 = (const uint4*)g_S;
    const size_t hstride = (size_t)8*8*128*64;             // uint4 per h
    size_t base0 = ((size_t)(b*128 + bxf)*8 + wid)*8192;   // uint4 units (h=0)
    float* am0 = am + ((size_t)b*Sc + Q0 + r0)*Sc;
    float* am1 = am + ((size_t)b*Sc + Q0 + r1)*Sc;

    for (int cb = slice*4; cb < slice*4 + 4; cb++) {
        float a00x=0,a00y=0,a10x=0,a10y=0,a01x=0,a01y=0,a11x=0,a11y=0;
        size_t addr = base0 + (size_t)(cb*4 + cq)*64 + k;
        #pragma unroll 4
        for (int h = 0; h < Hc; h++) {
            uint4 v = gS4[addr + (size_t)h*hstride];
            float w0 = wsum[h*32 + r0], w1 = wsum[h*32 + r1];
            float2 f0 = __half22float2(*(__half2*)&v.x);
            float2 f1 = __half22float2(*(__half2*)&v.y);
            float2 f2 = __half22float2(*(__half2*)&v.z);
            float2 f3 = __half22float2(*(__half2*)&v.w);
            a00x += f0.x*w0; a00y += f0.y*w0;
            a10x += f1.x*w1; a10y += f1.y*w1;
            a01x += f2.x*w0; a01y += f2.y*w0;
            a11x += f3.x*w1; a11y += f3.y*w1;
        }
        int colbase = cb*64 + cq*16;
        *(float2*)(am0 + colbase + 2*t)     = make_float2(a00x, a00y);
        *(float2*)(am1 + colbase + 2*t)     = make_float2(a10x, a10y);
        *(float2*)(am0 + colbase + 8 + 2*t) = make_float2(a01x, a01y);
        *(float2*)(am1 + colbase + 8 + 2*t) = make_float2(a11x, a11y);
    }
}

// ---------------- Output projection (fp16 HMMA, single pass Z x W) ----------------
#define SM_Z 0
#define SM_W 18432
#define SMEM_OP 36864

__device__ __forceinline__ void stage_op(char* smem, int off, const float4* gs,
                                         int base_row, int kc, int tid) {
    #pragma unroll
    for (int it = 0; it < 4; it++) {
        int i = tid + it*256;
        int r = i >> 3, c = i & 7;
        *(float4*)(smem + off + r*144 + c*16) = gs[(size_t)(base_row + r)*128 + kc*8 + c];
    }
}

__global__ __launch_bounds__(256,1) void out_proj_mma(
    const float* __restrict__ bz, float* __restrict__ out)
{
    extern __shared__ char smem[];
    uint32_t sb = (uint32_t)__cvta_generic_to_shared(smem);
    int tid = threadIdx.x, wid = tid >> 5, lane = tid & 31;
    int n0 = blockIdx.x*128, s0 = blockIdx.y*128;
    int t = lane & 3;
    int row0 = 16*wid + (lane >> 2);

    const float4* gz = (const float4*)g_Z;
    const float4* gw = (const float4*)g_Wz;

    float s[64];
    #pragma unroll
    for (int i = 0; i < 64; i++) s[i] = 0.f;

    for (int kc = 0; kc < 16; kc++) {
        if (kc) __syncthreads();
        stage_op(smem, SM_Z, gz, s0, kc, tid);
        stage_op(smem, SM_W, gw, n0, kc, tid);
        __syncthreads();

        #pragma unroll
        for (int ks = 0; ks < 4; ks++) {
            uint32_t aaddr = sb + SM_Z + (16*wid + (lane & 15))*144 + ks*32 + ((lane >> 4) << 4);
            uint32_t ah[4];
            ldm4(aaddr, ah);
            #pragma unroll
            for (int nb2 = 0; nb2 < 8; nb2++) {
                uint32_t baddr = sb + SM_W + (nb2*16 + (lane & 7) + ((lane >> 4) << 3))*144
                               + ks*32 + (((lane >> 3) & 1) << 4);
                uint32_t bhf[4];
                ldm4(baddr, bhf);
                mma16816h(s + (2*nb2)*4,   ah, bhf[0], bhf[1]);
                mma16816h(s + (2*nb2+1)*4, ah, bhf[2], bhf[3]);
            }
        }
    }

    float* o0 = out + (size_t)(s0 + row0)*Dc + n0;
    float* o1 = o0 + (size_t)8*Dc;
    #pragma unroll
    for (int nb = 0; nb < 16; nb++) {
        int col = nb*8 + 2*t;
        float b0 = bz[n0 + col], b1 = bz[n0 + col + 1];
        *(float2*)(o0 + col) = make_float2(s[nb*4+0] + b0, s[nb*4+1] + b1);
        *(float2*)(o1 + col) = make_float2(s[nb*4+2] + b0, s[nb*4+3] + b1);
    }
}

extern "C" void kernel_launch(void* const* d_in, const int* in_sizes, int n_in,
                              void* d_out, int out_size)
{
    const float* Xq = (const float*)d_in[0];
    const float* Xk = (const float*)d_in[1];
    const float* Xv = (const float*)d_in[2];
    const float* Wq = (const float*)d_in[3];
    const float* Wk = (const float*)d_in[4];
    const float* Wv = (const float*)d_in[5];
    const float* Wz = (const float*)d_in[6];
    const float* bz = (const float*)d_in[7];
    float* out  = (float*)d_out;
    float* attn = out + (size_t)Bc*Sc*Dc;   // out first, then attn_mean

    cudaFuncSetAttribute((const void*)qkv_mma,
                         cudaFuncAttributeMaxDynamicSharedMemorySize, SMEM_QP);
    cudaFuncSetAttribute((const void*)flash_attn,
                         cudaFuncAttributeMaxDynamicSharedMemorySize, SMEM_FL);
    cudaFuncSetAttribute((const void*)out_proj_mma,
                         cudaFuncAttributeMaxDynamicSharedMemorySize, SMEM_OP);

    w3_convert<<<dim3(64, 3), 256>>>(Wq, Wk, Wv);
    wz_convert<<<Dc*Dc/1024, 256>>>(Wz);
    qkv_mma<<<dim3(Sc/128, Hc, Bc), 256, SMEM_QP>>>(Xq, Xk, Xv);
    flash_attn<<<dim3(Sc/256, Hc, Bc), 256, SMEM_FL>>>();
    attn_mean_kernel<<<dim3(512, Bc), 256>>>(attn);
    out_proj_mma<<<dim3(Dc/128, (Bc*Sc)/128), 256, SMEM_OP>>>(bz, out);
}